// round 13
// baseline (speedup 1.0000x reference)
#include <cuda_runtime.h>
#include <cstdint>

typedef unsigned long long ull;

__constant__ float cCC[6]  = {0.f, 0.2f, 0.3f, 0.8f, (float)(8.0/9.0), 1.0f};
__constant__ float cBWv[6] = {(float)(35.0/384.0), 0.f, (float)(500.0/1113.0),
                              (float)(125.0/192.0), (float)(-2187.0/6784.0),
                              (float)(11.0/84.0)};

// ---- smem layout (float offsets), static 41KB ----
#define oXs  0        /* [s:4][128] = 512 */
#define oA   512      /* 512 */
#define oHP  1024     /* [ko:8][s:4][128] = 4096 */
#define oPb  5120     /* exchange [p:2][rank:4][512] = 4096 */
#define oStg 9216     /* staging [p:2][512] = 1024 */
#define oScr 10240    /* 32 */
#define oTx  10272    /* 4 */
#define oLp  10276    /* 4 */
#define SMF  10280

__device__ __forceinline__ ull mk2(float a, float b) {
  ull r; asm("mov.b64 %0, {%1, %2};" : "=l"(r) : "f"(a), "f"(b)); return r;
}
__device__ __forceinline__ float lo32(ull v) { return __uint_as_float((unsigned)v); }
__device__ __forceinline__ float hi32(ull v) { return __uint_as_float((unsigned)(v >> 32)); }
__device__ __forceinline__ ull f2fma(ull a, ull b, ull c) {
  ull d; asm("fma.rn.f32x2 %0,%1,%2,%3;" : "=l"(d) : "l"(a), "l"(b), "l"(c)); return d;
}
__device__ __forceinline__ float wsum(float v) {
#pragma unroll
  for (int o = 16; o > 0; o >>= 1) v += __shfl_xor_sync(0xffffffffu, v, o);
  return v;
}
__device__ __forceinline__ uint32_t smem_u32(const void* p) {
  uint32_t a;
  asm("{.reg .u64 t; cvta.to.shared.u64 t, %1; cvt.u32.u64 %0, t;}" : "=r"(a) : "l"(p));
  return a;
}
__device__ __forceinline__ uint32_t mapa_u32(uint32_t addr, uint32_t rank) {
  uint32_t ra; asm("mapa.shared::cluster.u32 %0, %1, %2;" : "=r"(ra) : "r"(addr), "r"(rank));
  return ra;
}
__device__ __forceinline__ float ldcf(uint32_t addr, uint32_t rank) {
  uint32_t ra = mapa_u32(addr, rank);
  float v; asm volatile("ld.shared::cluster.f32 %0, [%1];" : "=f"(v) : "r"(ra)); return v;
}
__device__ __forceinline__ void csync() {
  asm volatile("barrier.cluster.arrive.aligned;" ::: "memory");
  asm volatile("barrier.cluster.wait.aligned;" ::: "memory");
}
__device__ __forceinline__ void mbar_init(uint32_t mb, unsigned cnt) {
  asm volatile("mbarrier.init.shared::cta.b64 [%0], %1;" :: "r"(mb), "r"(cnt) : "memory");
}
__device__ __forceinline__ void mbar_arm(uint32_t mb, unsigned tx) {
  asm volatile("mbarrier.arrive.expect_tx.shared::cta.b64 _, [%0], %1;"
               :: "r"(mb), "r"(tx) : "memory");
}
__device__ __forceinline__ void bulk_copy128(uint32_t dst_cluster, uint32_t src_cta,
                                             uint32_t rmb_cluster) {
  asm volatile(
      "cp.async.bulk.shared::cluster.shared::cta.mbarrier::complete_tx::bytes "
      "[%0], [%1], 128, [%2];"
      :: "r"(dst_cluster), "r"(src_cta), "r"(rmb_cluster) : "memory");
}
// CTA-scope acquire (async-proxy data lands in OUR smem)
__device__ __forceinline__ void waitp(uint32_t mb, unsigned ph) {
  unsigned done;
  asm volatile(
      "{\n\t.reg .pred p;\n\t"
      "mbarrier.try_wait.parity.acquire.cta.shared::cta.b64 p, [%1], %2;\n\t"
      "selp.u32 %0,1,0,p;\n\t}"
      : "=r"(done) : "r"(mb), "r"(ph) : "memory");
  while (!done) {
    asm volatile(
        "{\n\t.reg .pred p;\n\t"
        "mbarrier.try_wait.parity.acquire.cta.shared::cta.b64 p, [%1], %2, 0x989680;\n\t"
        "selp.u32 %0,1,0,p;\n\t}"
        : "=r"(done) : "r"(mb), "r"(ph) : "memory");
  }
}
__device__ __forceinline__ float ftanh(float x) {
  float e = __expf(2.f * x);
  return 1.f - __fdividef(2.f, e + 1.f);
}

// GEMM octant: thread (cq = t&63, ko = t>>6) computes output cols {cq, cq+64}
// for 4 samples over k in [16ko, 16ko+16). Weights k-pair packed.
// src: [s:4][128]; dst: [ko:8][s:4][128].
__device__ __forceinline__ void gemm_o(const ull (&w)[2][8],
                                       const float* __restrict__ src,
                                       float* __restrict__ dst, int ko, int cq) {
  const float* sp = src + (ko << 4);
  float* dbase = dst + (ko << 9);
#pragma unroll
  for (int s = 0; s < 4; ++s) {
    ulonglong2 xa = *(const ulonglong2*)(sp + s * 128);       // k 0..3
    ulonglong2 xb = *(const ulonglong2*)(sp + s * 128 + 4);   // k 4..7
    ulonglong2 xc = *(const ulonglong2*)(sp + s * 128 + 8);   // k 8..11
    ulonglong2 xd = *(const ulonglong2*)(sp + s * 128 + 12);  // k 12..15
    ull a0 = 0, a1 = 0;
    a0 = f2fma(w[0][0], xa.x, a0); a1 = f2fma(w[1][0], xa.x, a1);
    a0 = f2fma(w[0][1], xa.y, a0); a1 = f2fma(w[1][1], xa.y, a1);
    a0 = f2fma(w[0][2], xb.x, a0); a1 = f2fma(w[1][2], xb.x, a1);
    a0 = f2fma(w[0][3], xb.y, a0); a1 = f2fma(w[1][3], xb.y, a1);
    a0 = f2fma(w[0][4], xc.x, a0); a1 = f2fma(w[1][4], xc.x, a1);
    a0 = f2fma(w[0][5], xc.y, a0); a1 = f2fma(w[1][5], xc.y, a1);
    a0 = f2fma(w[0][6], xd.x, a0); a1 = f2fma(w[1][6], xd.x, a1);
    a0 = f2fma(w[0][7], xd.y, a0); a1 = f2fma(w[1][7], xd.y, a1);
    float* d0 = dbase + s * 128;
    d0[cq]      = lo32(a0) + hi32(a0);
    d0[cq + 64] = lo32(a1) + hi32(a1);
  }
}

__global__ void __launch_bounds__(512, 1) __cluster_dims__(4, 1, 1)
vino_kernel(const float* __restrict__ x0g, const float* __restrict__ W1g,
            const float* __restrict__ b1g, const float* __restrict__ u1g,
            const float* __restrict__ W2g, const float* __restrict__ b2g,
            const int* __restrict__ nsp, float* __restrict__ out, int B) {
  __shared__ __align__(16) float sm[SMF];
  __shared__ __align__(8) unsigned long long smbar[2];
  const int t = threadIdx.x;
  const int w = t >> 5, lane = t & 31;
  const int cq = t & 63, ko = t >> 6;     // GEMM tiling (512 threads)
  const int c = t & 127, s = t >> 7;      // epilogue element (s, c)
  uint32_t rank; asm("mov.u32 %0, %%cluster_ctarank;" : "=r"(rank));
  const int hbase = (int)rank << 7;
  const int sb = (blockIdx.x >> 2) << 2;

  // ---- persistent k-pair-packed weights: 2 cols x 8 k-pairs per GEMM ----
  ull w1p[2][8], w2p[2][8];
#pragma unroll
  for (int i = 0; i < 8; ++i) {
    const int k0 = (ko << 4) + 2 * i;
    w1p[0][i] = mk2(W1g[k0 * 512 + hbase + cq],      W1g[(k0 + 1) * 512 + hbase + cq]);
    w1p[1][i] = mk2(W1g[k0 * 512 + hbase + cq + 64], W1g[(k0 + 1) * 512 + hbase + cq + 64]);
    w2p[0][i] = mk2(W2g[(hbase + k0) * 128 + cq],      W2g[(hbase + k0 + 1) * 128 + cq]);
    w2p[1][i] = mk2(W2g[(hbase + k0) * 128 + cq + 64], W2g[(hbase + k0 + 1) * 128 + cq + 64]);
  }

  // ---- per-element constants + scalar state ----
  const float b1r = b1g[hbase + c];
  const float u1r = u1g[hbase + c];
  const float b2r = b2g[c];
  float mr = 0.f;
#pragma unroll 4
  for (int i = 0; i < 128; ++i)
    mr = fmaf(W1g[i * 512 + hbase + c], W2g[(hbase + c) * 128 + i], mr);
  float y = x0g[(sb + s) * 128 + c];
  float xs = y;
  sm[oXs + s * 128 + c] = xs;

  // ---- mbarriers + bulk-copy addresses ----
  const uint32_t mb0 = smem_u32(&smbar[0]);
  if (t == 0) {
    mbar_init(mb0, 1); mbar_init(mb0 + 8, 1);
    mbar_arm(mb0, 8192u); mbar_arm(mb0 + 8, 8192u);  // 4 ranks x 2KB
  }
  const uint32_t stgb = smem_u32(sm + oStg);
  uint32_t dstb[4], rmbb[4];
  {
    // my 128B warp chunk inside each rank's Pb: [rank][w*32 .. w*32+32) floats
    const uint32_t doff = smem_u32(sm + oPb) + ((uint32_t)rank << 11) + ((uint32_t)w << 7);
#pragma unroll
    for (uint32_t r = 0; r < 4; ++r) {
      dstb[r] = mapa_u32(doff, r);
      rmbb[r] = mapa_u32(mb0, r);
    }
  }

  // ---- log p(x0) ----
  {
    float ss = wsum(y * y);
    if (lane == 0) sScrW: sm[oScr + w] = ss;
  }
  __syncthreads();
  if (t < 4) {
    float ss = sm[oScr + 4 * t] + sm[oScr + 4 * t + 1] +
               sm[oScr + 4 * t + 2] + sm[oScr + 4 * t + 3];
    sm[oLp + t] = -0.5f * ss - 117.6241322501981f;  // 64*log(2*pi)
  }
  csync();  // mbar arming + smem init visible cluster-wide

  const int ns = *nsp;
  const float dt = 1.0f / (float)ns;
  float ks0 = 0.f, ks1 = 0.f, ks2 = 0.f, ks3 = 0.f, ks4 = 0.f;
  float tr = 0.f, dot = 0.f;
  unsigned par0 = 0, par1 = 0;

  for (int step = 0; step < ns; ++step) {
    const float tstep = (float)step * dt;
#pragma unroll 1
    for (int stage = 0; stage < 6; ++stage) {
      const float coef = dt * cBWv[stage];
      const float tcur = tstep + cCC[stage] * dt;
      const int p = stage & 1;

      __syncthreads();                  // S_A: sXs visible
      gemm_o(w1p, sm + oXs, sm + oHP, ko, cq);
      __syncthreads();                  // S_B

      // tanh + trace (one element per thread)
      {
        float h = fmaf(tcur, u1r, b1r);
#pragma unroll
        for (int q = 0; q < 8; ++q) h += sm[oHP + (q << 9) + s * 128 + c];
        float a = ftanh(h);
        sm[oA + s * 128 + c] = a;
        tr = fmaf((1.f - a * a) * mr, coef, tr);
      }
      __syncthreads();                  // S_C
      gemm_o(w2p, sm + oA, sm + oHP, ko, cq);
      __syncthreads();                  // S_D

      // fold partials into parity staging; lane 0 bulk-pushes warp's 128B
      {
        float v = 0.f;
#pragma unroll
        for (int q = 0; q < 8; ++q) v += sm[oHP + (q << 9) + s * 128 + c];
        sm[oStg + (p << 9) + t] = v;
        __syncwarp();
        if (lane == 0) {
          asm volatile("fence.proxy.async.shared::cta;" ::: "memory");
          const uint32_t src = stgb + ((uint32_t)p << 11) + ((uint32_t)w << 7);
          const uint32_t dof = (uint32_t)p << 13;   // p * 8192 B
          const uint32_t mof = (uint32_t)p << 3;
          bulk_copy128(dstb[0] + dof, src, rmbb[0] + mof);
          bulk_copy128(dstb[1] + dof, src, rmbb[1] + mof);
          bulk_copy128(dstb[2] + dof, src, rmbb[2] + mof);
          bulk_copy128(dstb[3] + dof, src, rmbb[3] + mof);
        }
      }

      // wait for all 8KB of this buffer, re-arm
      {
        const uint32_t lmb = mb0 + (p << 3);
        unsigned ph = p ? par1 : par0;
        waitp(lmb, ph);
        if (p) par1 ^= 1; else par0 ^= 1;
        if (t == 0) mbar_arm(lmb, 8192u);
      }

      // assemble dxdt, dot, advance RK state (scalar registers)
      {
        const float* pb = sm + oPb + (p << 11);
        float k = ((pb[t] + pb[512 + t]) + (pb[1024 + t] + pb[1536 + t])) + b2r;
        dot = fmaf(xs * k, coef, dot);
        float acc;
        switch (stage) {
          case 0:
            ks0 = k; acc = 0.2f * ks0; break;
          case 1:
            ks1 = k;
            acc = fmaf(0.225f, ks1, 0.075f * ks0);
            break;
          case 2:
            ks2 = k;
            acc = (float)(44.0 / 45.0) * ks0;
            acc = fmaf((float)(-56.0 / 15.0), ks1, acc);
            acc = fmaf((float)(32.0 / 9.0), ks2, acc);
            break;
          case 3:
            ks3 = k;
            acc = (float)(19372.0 / 6561.0) * ks0;
            acc = fmaf((float)(-25360.0 / 2187.0), ks1, acc);
            acc = fmaf((float)(64448.0 / 6561.0), ks2, acc);
            acc = fmaf((float)(-212.0 / 729.0), ks3, acc);
            break;
          case 4:
            ks4 = k;
            acc = (float)(9017.0 / 3168.0) * ks0;
            acc = fmaf((float)(-355.0 / 33.0), ks1, acc);
            acc = fmaf((float)(46732.0 / 5247.0), ks2, acc);
            acc = fmaf((float)(49.0 / 176.0), ks3, acc);
            acc = fmaf((float)(-5103.0 / 18656.0), ks4, acc);
            break;
          default:
            acc = (float)(35.0 / 384.0) * ks0;
            acc = fmaf((float)(500.0 / 1113.0), ks2, acc);
            acc = fmaf((float)(125.0 / 192.0), ks3, acc);
            acc = fmaf((float)(-2187.0 / 6784.0), ks4, acc);
            acc = fmaf((float)(11.0 / 84.0), k, acc);
            break;
        }
        if (stage == 5) { y = fmaf(dt, acc, y); xs = y; }
        else            { xs = fmaf(dt, acc, y); }
        sm[oXs + s * 128 + c] = xs;
      }
    }
  }

  // ---- outputs: z ----
  out[(sb + s) * 128 + c] = y;

  // ---- final reductions ----
  {
    float tw = wsum(tr), dw = wsum(dot);
    if (lane == 0) { sm[oScr + w] = tw; sm[oScr + 16 + w] = dw; }
  }
  __syncthreads();
  if (t < 4) {
    float T = sm[oScr + 4 * t] + sm[oScr + 4 * t + 1] +
              sm[oScr + 4 * t + 2] + sm[oScr + 4 * t + 3];
    float D = sm[oScr + 16 + 4 * t] + sm[oScr + 17 + 4 * t] +
              sm[oScr + 18 + 4 * t] + sm[oScr + 19 + 4 * t];
    sm[oTx + t] = T;
    sm[oScr + t] = D;  // safe: this thread already read its inputs
  }
  csync();
  if (t < 4) {
    const uint32_t ta = smem_u32(&sm[oTx + t]);
    float T4 = 0.f;
#pragma unroll
    for (uint32_t r = 0; r < 4; ++r) T4 += ldcf(ta, r);
    out[B * 128 + sb + t]     = sm[oLp + t] - T4;   // log_px
    out[B * 128 + B + sb + t] = sm[oScr + t] - T4;  // kl
  }
  csync();  // keep smem alive until peers finish remote reads
}

extern "C" void kernel_launch(void* const* d_in, const int* in_sizes, int n_in,
                              void* d_out, int out_size) {
  const float* x0 = (const float*)d_in[0];
  const float* W1 = (const float*)d_in[1];
  const float* b1 = (const float*)d_in[2];
  const float* u1 = (const float*)d_in[3];
  const float* W2 = (const float*)d_in[4];
  const float* b2 = (const float*)d_in[5];
  const int*   ns = (const int*)d_in[6];
  float* out = (float*)d_out;
  int B = in_sizes[0] / 128;
  vino_kernel<<<B, 512>>>(x0, W1, b1, u1, W2, b2, ns, out, B);
}